// round 9
// baseline (speedup 1.0000x reference)
#include <cuda_runtime.h>
#include <cuda_bf16.h>
#include <mma.h>
#include <cstdint>
#include <cstddef>

using namespace nvcuda;

#define BB   2
#define LL   512
#define HIN  1024
#define ENT  16
#define DD   50
#define TOT  850
#define PADN 896
#define NMASK 511
#define SCALE 0.14142135623730951f

// ---------------------------------------------------------------------------
// Scratch (device globals)
// ---------------------------------------------------------------------------
__device__ __nv_bfloat16 g_Xh[1024 * 1024];
__device__ __nv_bfloat16 g_Xl[1024 * 1024];
__device__ __nv_bfloat16 g_WhT[2 * PADN * HIN];   // [z][n][k]
__device__ __nv_bfloat16 g_WlT[2 * PADN * HIN];
__device__ float g_proj_s[BB * (ENT + 1) * LL * DD];
__device__ float g_proj_e[BB * (ENT + 1) * LL * DD];
__device__ float g_cd[BB * NMASK];
__device__ float g_tcos[LL * (DD / 2)];
__device__ float g_tsin[LL * (DD / 2)];

// ---------------------------------------------------------------------------
// Prep kernels
// ---------------------------------------------------------------------------
__global__ void split_x(const float* __restrict__ X)
{
    int idx = blockIdx.x * blockDim.x + threadIdx.x;
    if (idx >= 1024 * 1024) return;
    float x = X[idx];
    __nv_bfloat16 h = __float2bfloat16(x);
    __nv_bfloat16 l = __float2bfloat16(x - __bfloat162float(h));
    g_Xh[idx] = h;
    g_Xl[idx] = l;
}

__global__ void split_wT(const float* __restrict__ W0, const float* __restrict__ W1)
{
    __shared__ __nv_bfloat16 th[32][33];
    __shared__ __nv_bfloat16 tl[32][33];
    const int z = blockIdx.z;
    const float* W = z ? W1 : W0;
    const int n0 = blockIdx.x * 32;
    const int k0 = blockIdx.y * 32;
    const int tx = threadIdx.x, ty = threadIdx.y;

    int n = n0 + tx, k = k0 + ty;
    float x = (n < TOT) ? W[(size_t)k * TOT + n] : 0.f;
    __nv_bfloat16 h = __float2bfloat16(x);
    __nv_bfloat16 l = __float2bfloat16(x - __bfloat162float(h));
    th[ty][tx] = h;
    tl[ty][tx] = l;
    __syncthreads();

    int on = n0 + ty, ok = k0 + tx;
    size_t oidx = (size_t)z * PADN * HIN + (size_t)on * HIN + ok;
    g_WhT[oidx] = th[tx][ty];
    g_WlT[oidx] = tl[tx][ty];
}

__global__ void trig_table()
{
    int idx = blockIdx.x * blockDim.x + threadIdx.x;
    if (idx >= LL * (DD / 2)) return;
    int l = idx / (DD / 2), t = idx - l * (DD / 2);
    double inv = exp(-((2.0 * t) / (double)DD) * log(10000.0));
    double ang = (double)l * inv;
    g_tcos[idx] = (float)cos(ang);
    g_tsin[idx] = (float)sin(ang);
}

// ---------------------------------------------------------------------------
// WMMA bf16 GEMM, 64x64 tile, 448 blocks (3/SM), RoPE fused in epilogue.
// 3-term split: Ah*Bh + Ah*Bl + Al*Bh, fp32 accum.
// grid (14, 16, 2), 256 threads / 8 warps.
// warp: wr = wid&3 -> M 16-chunk, wc = wid>>2 -> N 32-chunk.
// ---------------------------------------------------------------------------
union GemmSmem {
    struct {
        __nv_bfloat16 Ah[64][40];
        __nv_bfloat16 Al[64][40];
        __nv_bfloat16 Bh[64][40];
        __nv_bfloat16 Bl[64][40];
    } t;
    float out[64][68];
};

__global__ __launch_bounds__(256) void gemm_wmma(
    const float* __restrict__ bias0, const float* __restrict__ bias1)
{
    __shared__ GemmSmem sm;

    const int z  = blockIdx.z;
    const int n0 = blockIdx.x * 64;
    const int m0 = blockIdx.y * 64;
    const float* bias = z ? bias1 : bias0;
    float* dst        = z ? g_proj_e : g_proj_s;

    const int tid = threadIdx.x;
    const int wid = tid >> 5;
    const int wr = wid & 3;        // M 16-chunk (0..3)
    const int wc = wid >> 2;       // N 32-chunk (0..1)

    const uint4* Xh4 = reinterpret_cast<const uint4*>(g_Xh);
    const uint4* Xl4 = reinterpret_cast<const uint4*>(g_Xl);
    const uint4* Bh4 = reinterpret_cast<const uint4*>(g_WhT) + (size_t)z * PADN * 128;
    const uint4* Bl4 = reinterpret_cast<const uint4*>(g_WlT) + (size_t)z * PADN * 128;

    wmma::fragment<wmma::accumulator, 16, 16, 16, float> c[2];
    wmma::fill_fragment(c[0], 0.f);
    wmma::fill_fragment(c[1], 0.f);

    const int lrow = tid >> 2, lc8 = tid & 3;   // one uint4 per thread per tile

    for (int kc = 0; kc < HIN; kc += 32) {
        const int kc8 = kc >> 3;
        {
            size_t gi = (size_t)(m0 + lrow) * 128 + kc8 + lc8;
            *reinterpret_cast<uint4*>(&sm.t.Ah[lrow][lc8 * 8]) = Xh4[gi];
            *reinterpret_cast<uint4*>(&sm.t.Al[lrow][lc8 * 8]) = Xl4[gi];
            size_t gb = (size_t)(n0 + lrow) * 128 + kc8 + lc8;
            *reinterpret_cast<uint4*>(&sm.t.Bh[lrow][lc8 * 8]) = Bh4[gb];
            *reinterpret_cast<uint4*>(&sm.t.Bl[lrow][lc8 * 8]) = Bl4[gb];
        }
        __syncthreads();

        #pragma unroll
        for (int ks = 0; ks < 32; ks += 16) {
            wmma::fragment<wmma::matrix_a, 16, 16, 16, __nv_bfloat16, wmma::row_major> ah, al;
            wmma::fragment<wmma::matrix_b, 16, 16, 16, __nv_bfloat16, wmma::col_major> bh[2], bl[2];
            wmma::load_matrix_sync(ah, &sm.t.Ah[wr * 16][ks], 40);
            wmma::load_matrix_sync(al, &sm.t.Al[wr * 16][ks], 40);
            #pragma unroll
            for (int j = 0; j < 2; j++) {
                wmma::load_matrix_sync(bh[j], &sm.t.Bh[wc * 32 + j * 16][ks], 40);
                wmma::load_matrix_sync(bl[j], &sm.t.Bl[wc * 32 + j * 16][ks], 40);
            }
            #pragma unroll
            for (int j = 0; j < 2; j++) {
                wmma::mma_sync(c[j], ah, bh[j], c[j]);
                wmma::mma_sync(c[j], ah, bl[j], c[j]);
                wmma::mma_sync(c[j], al, bh[j], c[j]);
            }
        }
        __syncthreads();
    }

    #pragma unroll
    for (int j = 0; j < 2; j++)
        wmma::store_matrix_sync(&sm.out[wr * 16][wc * 32 + j * 16],
                                c[j], 68, wmma::mem_row_major);
    __syncthreads();

    // Epilogue with fused RoPE: thread handles an even/odd column pair.
    // DD=50 is even, so (n, n+1) never straddles an e boundary.
    for (int idx = tid; idx < 64 * 32; idx += 256) {
        int row = idx >> 5, cp = idx & 31;
        int n = n0 + cp * 2;
        if (n < TOT) {
            int e = n / DD, d = n - e * DD;      // d even
            int m = m0 + row;
            int b = m >> 9, l = m & 511;
            float v0 = sm.out[row][cp * 2]     + bias[n];
            float v1 = sm.out[row][cp * 2 + 1] + bias[n + 1];
            if (e < ENT) {
                int t = d >> 1;
                float cc = g_tcos[l * (DD / 2) + t];
                float ss = g_tsin[l * (DD / 2) + t];
                float r0 = v0 * cc - v1 * ss;
                float r1 = v1 * cc + v0 * ss;
                v0 = r0; v1 = r1;
            }
            size_t o = (((size_t)b * (ENT + 1) + e) * LL + l) * DD + d;
            dst[o]     = v0;
            dst[o + 1] = v1;
        }
    }
}

// ---------------------------------------------------------------------------
// conj_diag — warp per (b,i), shfl reduce (uses un-roped e=16 slice)
// ---------------------------------------------------------------------------
__global__ __launch_bounds__(256) void conj_kernel()
{
    int wg = blockIdx.x * 8 + (threadIdx.x >> 5);
    int lane = threadIdx.x & 31;
    if (wg >= BB * NMASK) return;
    int b = wg / NMASK, i = wg - b * NMASK;
    const float* a = g_proj_s + (((size_t)b * (ENT + 1) + ENT) * LL + i) * DD;
    const float* c = g_proj_e + (((size_t)b * (ENT + 1) + ENT) * LL + (i + 1)) * DD;
    float s = 0.f;
    if (lane < DD)      s  = a[lane] * c[lane];
    if (lane + 32 < DD) s += a[lane + 32] * c[lane + 32];
    #pragma unroll
    for (int o = 16; o > 0; o >>= 1)
        s += __shfl_xor_sync(0xFFFFFFFFu, s, o);
    if (lane == 0) g_cd[wg] = s * SCALE;
}

// ---------------------------------------------------------------------------
// Fused mask-reduction + scores.
// Tile: 16 i x 32 j per 256-thread block, 512 blocks.
// Mask phase: float2 loads -> warp covers 2 full 128B lines per k (half the
// L1 wavefronts/byte of the scalar R1 version). Results stashed in sma[].
// Scores phase: R1 shape (16 e regs) over two j-halves of 16.
// ---------------------------------------------------------------------------
__global__ __launch_bounds__(256) void fused_kernel(
    const float* __restrict__ mask, float* __restrict__ out)
{
    __shared__ float scd[BB * NMASK];      // 4088 B
    __shared__ float sq[16 * DD];          // 3200 B
    __shared__ float sk[16 * DD];          // 3200 B
    __shared__ float sma[BB][16][32];      // 4096 B

    const int tid = threadIdx.x;
    const int tx = tid & 15;   // mask: j-pair index; scores: j offset in half
    const int ty = tid >> 4;   // i offset

    for (int k = tid; k < BB * NMASK; k += 256) scd[k] = g_cd[k];

    const int i0 = blockIdx.y * 16, j0 = blockIdx.x * 32;
    const int i = i0 + ty;
    const float* mp = mask + (size_t)i * LL + j0 + tx * 2;

    __syncthreads();

    // ---- mask reduction: float2 strided stream, unrolled x8 ----
    float2 a0 = make_float2(0.f, 0.f);
    float2 a1 = make_float2(0.f, 0.f);
    int k = 0;
    for (; k + 8 <= NMASK; k += 8) {
        float2 m[8];
        #pragma unroll
        for (int u = 0; u < 8; u++)
            m[u] = *reinterpret_cast<const float2*>(mp + (size_t)(k + u) * (LL * LL));
        #pragma unroll
        for (int u = 0; u < 8; u++) {
            float c0 = scd[k + u], c1 = scd[NMASK + k + u];
            a0.x = fmaf(c0, m[u].x, a0.x); a0.y = fmaf(c0, m[u].y, a0.y);
            a1.x = fmaf(c1, m[u].x, a1.x); a1.y = fmaf(c1, m[u].y, a1.y);
        }
    }
    for (; k < NMASK; k++) {
        float2 m = *reinterpret_cast<const float2*>(mp + (size_t)k * (LL * LL));
        float c0 = scd[k], c1 = scd[NMASK + k];
        a0.x = fmaf(c0, m.x, a0.x); a0.y = fmaf(c0, m.y, a0.y);
        a1.x = fmaf(c1, m.x, a1.x); a1.y = fmaf(c1, m.y, a1.y);
    }
    sma[0][ty][tx * 2]     = a0.x;
    sma[0][ty][tx * 2 + 1] = a0.y;
    sma[1][ty][tx * 2]     = a1.x;
    sma[1][ty][tx * 2 + 1] = a1.y;
    // visibility guaranteed by the __syncthreads at the top of the e-loop

    // ---- scores + epilogue: two j-halves of 16, R1 per-half shape ----
    for (int b = 0; b < BB; b++) {
        for (int half = 0; half < 2; half++) {
            const int j0h = j0 + half * 16;
            float sreg[ENT];
            for (int e = 0; e < ENT; e++) {
                __syncthreads();
                const float* qb = g_proj_s + (((size_t)b * (ENT + 1) + e) * LL + i0) * DD;
                const float* kb = g_proj_e + (((size_t)b * (ENT + 1) + e) * LL + j0h) * DD;
                for (int x = tid; x < 16 * DD; x += 256) {
                    sq[x] = qb[x];
                    sk[x] = kb[x];
                }
                __syncthreads();
                float dot = 0.f;
                #pragma unroll
                for (int d = 0; d < DD; d++)
                    dot = fmaf(sq[ty * DD + d], sk[tx * DD + d], dot);
                sreg[e] = dot * SCALE;
            }
            const float amask = sma[b][ty][half * 16 + tx];
            const int j = j0h + tx;
            float4* op = reinterpret_cast<float4*>(
                out + ((((size_t)b * LL + i) * LL + j) * ENT));
            #pragma unroll
            for (int v = 0; v < 4; v++)
                op[v] = make_float4(sreg[4 * v]     + amask,
                                    sreg[4 * v + 1] + amask,
                                    sreg[4 * v + 2] + amask,
                                    sreg[4 * v + 3] + amask);
        }
    }
}

// ---------------------------------------------------------------------------
extern "C" void kernel_launch(void* const* d_in, const int* in_sizes, int n_in,
                              void* d_out, int out_size)
{
    const float* X    = (const float*)d_in[0];
    const float* mask = (const float*)d_in[1];
    const float* Ws   = (const float*)d_in[2];
    const float* bs   = (const float*)d_in[3];
    const float* We   = (const float*)d_in[4];
    const float* be   = (const float*)d_in[5];
    float* out        = (float*)d_out;

    split_x<<<(1024 * 1024 + 255) / 256, 256>>>(X);
    split_wT<<<dim3(PADN / 32, HIN / 32, 2), dim3(32, 32)>>>(Ws, We);
    trig_table<<<(LL * (DD / 2) + 255) / 256, 256>>>();

    gemm_wmma<<<dim3(PADN / 64, 1024 / 64, 2), 256>>>(bs, be);

    conj_kernel<<<(BB * NMASK + 7) / 8, 256>>>();

    fused_kernel<<<dim3(LL / 32, LL / 16), 256>>>(mask, out);
}

// round 10
// speedup vs baseline: 1.1907x; 1.1907x over previous
#include <cuda_runtime.h>
#include <cuda_bf16.h>
#include <mma.h>
#include <cstdint>
#include <cstddef>

using namespace nvcuda;

#define BB   2
#define LL   512
#define HIN  1024
#define ENT  16
#define DD   50
#define TOT  850
#define PADN 896
#define NMASK 511
#define SCALE 0.14142135623730951f

// ---------------------------------------------------------------------------
// Scratch (device globals)
// ---------------------------------------------------------------------------
__device__ __nv_bfloat16 g_Xh[1024 * 1024];
__device__ __nv_bfloat16 g_Xl[1024 * 1024];
__device__ __nv_bfloat16 g_WhT[2 * PADN * HIN];   // [z][n][k]
__device__ __nv_bfloat16 g_WlT[2 * PADN * HIN];
__device__ float g_proj_s[BB * (ENT + 1) * LL * DD];
__device__ float g_proj_e[BB * (ENT + 1) * LL * DD];
__device__ float g_cd[BB * NMASK];
__device__ float g_tcos[LL * (DD / 2)];
__device__ float g_tsin[LL * (DD / 2)];

// ---------------------------------------------------------------------------
// Prep kernels
// ---------------------------------------------------------------------------
__global__ void split_x(const float* __restrict__ X)
{
    int idx = blockIdx.x * blockDim.x + threadIdx.x;
    if (idx >= 1024 * 1024) return;
    float x = X[idx];
    __nv_bfloat16 h = __float2bfloat16(x);
    __nv_bfloat16 l = __float2bfloat16(x - __bfloat162float(h));
    g_Xh[idx] = h;
    g_Xl[idx] = l;
}

__global__ void split_wT(const float* __restrict__ W0, const float* __restrict__ W1)
{
    __shared__ __nv_bfloat16 th[32][33];
    __shared__ __nv_bfloat16 tl[32][33];
    const int z = blockIdx.z;
    const float* W = z ? W1 : W0;
    const int n0 = blockIdx.x * 32;
    const int k0 = blockIdx.y * 32;
    const int tx = threadIdx.x, ty = threadIdx.y;

    int n = n0 + tx, k = k0 + ty;
    float x = (n < TOT) ? W[(size_t)k * TOT + n] : 0.f;
    __nv_bfloat16 h = __float2bfloat16(x);
    __nv_bfloat16 l = __float2bfloat16(x - __bfloat162float(h));
    th[ty][tx] = h;
    tl[ty][tx] = l;
    __syncthreads();

    int on = n0 + ty, ok = k0 + tx;
    size_t oidx = (size_t)z * PADN * HIN + (size_t)on * HIN + ok;
    g_WhT[oidx] = th[tx][ty];
    g_WlT[oidx] = tl[tx][ty];
}

__global__ void trig_table()
{
    int idx = blockIdx.x * blockDim.x + threadIdx.x;
    if (idx >= LL * (DD / 2)) return;
    int l = idx / (DD / 2), t = idx - l * (DD / 2);
    double inv = exp(-((2.0 * t) / (double)DD) * log(10000.0));
    double ang = (double)l * inv;
    g_tcos[idx] = (float)cos(ang);
    g_tsin[idx] = (float)sin(ang);
}

// ---------------------------------------------------------------------------
// WMMA bf16 GEMM (R8 128x64 config, 72us measured) + RoPE fused in epilogue.
// ---------------------------------------------------------------------------
union GemmSmem {
    struct {
        __nv_bfloat16 Ah[128][40];
        __nv_bfloat16 Al[128][40];
        __nv_bfloat16 Bh[64][40];
        __nv_bfloat16 Bl[64][40];
    } t;
    float out[128][68];
};

__global__ __launch_bounds__(256) void gemm_wmma(
    const float* __restrict__ bias0, const float* __restrict__ bias1)
{
    __shared__ GemmSmem sm;

    const int z  = blockIdx.z;
    const int n0 = blockIdx.x * 64;
    const int m0 = blockIdx.y * 128;
    const float* bias = z ? bias1 : bias0;
    float* dst        = z ? g_proj_e : g_proj_s;

    const int tid = threadIdx.x;
    const int wid = tid >> 5;
    const int wr = wid >> 1;
    const int wc = wid & 1;

    const uint4* Xh4 = reinterpret_cast<const uint4*>(g_Xh);
    const uint4* Xl4 = reinterpret_cast<const uint4*>(g_Xl);
    const uint4* Bh4 = reinterpret_cast<const uint4*>(g_WhT) + (size_t)z * PADN * 128;
    const uint4* Bl4 = reinterpret_cast<const uint4*>(g_WlT) + (size_t)z * PADN * 128;

    wmma::fragment<wmma::accumulator, 16, 16, 16, float> c[2][2];
    #pragma unroll
    for (int i = 0; i < 2; i++)
        #pragma unroll
        for (int j = 0; j < 2; j++)
            wmma::fill_fragment(c[i][j], 0.f);

    for (int kc = 0; kc < HIN; kc += 32) {
        const int kc8 = kc >> 3;
        #pragma unroll
        for (int it = 0; it < 2; it++) {
            int u = it * 256 + tid;
            int row = u >> 2, c8 = u & 3;
            size_t gi = (size_t)(m0 + row) * 128 + kc8 + c8;
            *reinterpret_cast<uint4*>(&sm.t.Ah[row][c8 * 8]) = Xh4[gi];
            *reinterpret_cast<uint4*>(&sm.t.Al[row][c8 * 8]) = Xl4[gi];
        }
        {
            int row = tid >> 2, c8 = tid & 3;
            size_t gi = (size_t)(n0 + row) * 128 + kc8 + c8;
            *reinterpret_cast<uint4*>(&sm.t.Bh[row][c8 * 8]) = Bh4[gi];
            *reinterpret_cast<uint4*>(&sm.t.Bl[row][c8 * 8]) = Bl4[gi];
        }
        __syncthreads();

        #pragma unroll
        for (int ks = 0; ks < 32; ks += 16) {
            wmma::fragment<wmma::matrix_a, 16, 16, 16, __nv_bfloat16, wmma::row_major> ah[2], al[2];
            wmma::fragment<wmma::matrix_b, 16, 16, 16, __nv_bfloat16, wmma::col_major> bh[2], bl[2];
            #pragma unroll
            for (int i = 0; i < 2; i++) {
                wmma::load_matrix_sync(ah[i], &sm.t.Ah[wr * 32 + i * 16][ks], 40);
                wmma::load_matrix_sync(al[i], &sm.t.Al[wr * 32 + i * 16][ks], 40);
            }
            #pragma unroll
            for (int j = 0; j < 2; j++) {
                wmma::load_matrix_sync(bh[j], &sm.t.Bh[wc * 32 + j * 16][ks], 40);
                wmma::load_matrix_sync(bl[j], &sm.t.Bl[wc * 32 + j * 16][ks], 40);
            }
            #pragma unroll
            for (int i = 0; i < 2; i++)
                #pragma unroll
                for (int j = 0; j < 2; j++) {
                    wmma::mma_sync(c[i][j], ah[i], bh[j], c[i][j]);
                    wmma::mma_sync(c[i][j], ah[i], bl[j], c[i][j]);
                    wmma::mma_sync(c[i][j], al[i], bh[j], c[i][j]);
                }
        }
        __syncthreads();
    }

    #pragma unroll
    for (int i = 0; i < 2; i++)
        #pragma unroll
        for (int j = 0; j < 2; j++)
            wmma::store_matrix_sync(&sm.out[wr * 32 + i * 16][wc * 32 + j * 16],
                                    c[i][j], 68, wmma::mem_row_major);
    __syncthreads();

    // Epilogue with fused RoPE: thread handles an even/odd column pair.
    // DD=50 even -> a pair never straddles an e boundary; d is even.
    for (int idx = tid; idx < 128 * 32; idx += 256) {
        int row = idx >> 5, cp = idx & 31;
        int n = n0 + cp * 2;
        if (n < TOT) {
            int e = n / DD, d = n - e * DD;
            int m = m0 + row;
            int b = m >> 9, l = m & 511;
            float v0 = sm.out[row][cp * 2]     + bias[n];
            float v1 = sm.out[row][cp * 2 + 1] + bias[n + 1];
            if (e < ENT) {
                int t = d >> 1;
                float cc = g_tcos[l * (DD / 2) + t];
                float ss = g_tsin[l * (DD / 2) + t];
                float r0 = v0 * cc - v1 * ss;
                float r1 = v1 * cc + v0 * ss;
                v0 = r0; v1 = r1;
            }
            size_t o = (((size_t)b * (ENT + 1) + e) * LL + l) * DD + d;
            dst[o]     = v0;
            dst[o + 1] = v1;
        }
    }
}

// ---------------------------------------------------------------------------
// conj_diag — warp per (b,i), shfl reduce (e=16 slice is never roped)
// ---------------------------------------------------------------------------
__global__ __launch_bounds__(256) void conj_kernel()
{
    int wg = blockIdx.x * 8 + (threadIdx.x >> 5);
    int lane = threadIdx.x & 31;
    if (wg >= BB * NMASK) return;
    int b = wg / NMASK, i = wg - b * NMASK;
    const float* a = g_proj_s + (((size_t)b * (ENT + 1) + ENT) * LL + i) * DD;
    const float* c = g_proj_e + (((size_t)b * (ENT + 1) + ENT) * LL + (i + 1)) * DD;
    float s = 0.f;
    if (lane < DD)      s  = a[lane] * c[lane];
    if (lane + 32 < DD) s += a[lane + 32] * c[lane + 32];
    #pragma unroll
    for (int o = 16; o > 0; o >>= 1)
        s += __shfl_xor_sync(0xFFFFFFFFu, s, o);
    if (lane == 0) g_cd[wg] = s * SCALE;
}

// ---------------------------------------------------------------------------
// Fused mask-reduction + scores — EXACT R1 thread mapping (measured 194.8us);
// ONLY change: the score dot-product uses float2 LDS (halves smem traffic,
// which is what keeps blocks out of the DRAM-streaming phase).
// ---------------------------------------------------------------------------
__global__ __launch_bounds__(256) void fused_kernel(
    const float* __restrict__ mask, float* __restrict__ out)
{
    __shared__ float scd[BB * NMASK];     // 1022
    __shared__ float sq[16 * DD];         // 800
    __shared__ float sk[16 * DD];

    const int tid = threadIdx.x;
    const int tx = tid & 15;   // j offset
    const int ty = tid >> 4;   // i offset

    for (int k = tid; k < BB * NMASK; k += 256) scd[k] = g_cd[k];

    const int i0 = blockIdx.y * 16, j0 = blockIdx.x * 16;
    const int i = i0 + ty, j = j0 + tx;
    const float* mp = mask + (size_t)i * LL + j;

    __syncthreads();

    // ---- mask reduction: 511 strided loads, unrolled x8 for MLP ----
    float a0 = 0.f, a1 = 0.f;
    int k = 0;
    for (; k + 8 <= NMASK; k += 8) {
        float m[8];
        #pragma unroll
        for (int u = 0; u < 8; u++) m[u] = mp[(size_t)(k + u) * (LL * LL)];
        #pragma unroll
        for (int u = 0; u < 8; u++) {
            a0 = fmaf(scd[k + u],          m[u], a0);
            a1 = fmaf(scd[NMASK + k + u],  m[u], a1);
        }
    }
    for (; k < NMASK; k++) {
        float m = mp[(size_t)k * (LL * LL)];
        a0 = fmaf(scd[k],         m, a0);
        a1 = fmaf(scd[NMASK + k], m, a1);
    }

    // ---- scores + epilogue ----
    for (int b = 0; b < BB; b++) {
        float sreg[ENT];
        const float amask = b ? a1 : a0;
        for (int e = 0; e < ENT; e++) {
            __syncthreads();
            const float* qb = g_proj_s + (((size_t)b * (ENT + 1) + e) * LL + i0) * DD;
            const float* kb = g_proj_e + (((size_t)b * (ENT + 1) + e) * LL + j0) * DD;
            for (int x = tid; x < 16 * DD; x += 256) {
                sq[x] = qb[x];
                sk[x] = kb[x];
            }
            __syncthreads();
            // float2 LDS: rows are 50 floats = 200B (8B-aligned); 25 LDS.64
            // per operand instead of 50 LDS.32.
            const float2* qp = reinterpret_cast<const float2*>(&sq[ty * DD]);
            const float2* kp = reinterpret_cast<const float2*>(&sk[tx * DD]);
            float dot = 0.f;
            #pragma unroll
            for (int d = 0; d < DD / 2; d++) {
                float2 qv = qp[d];
                float2 kv = kp[d];
                dot = fmaf(qv.x, kv.x, dot);
                dot = fmaf(qv.y, kv.y, dot);
            }
            sreg[e] = dot * SCALE + amask;
        }
        float4* op = reinterpret_cast<float4*>(
            out + ((((size_t)b * LL + i) * LL + j) * ENT));
        #pragma unroll
        for (int v = 0; v < 4; v++)
            op[v] = make_float4(sreg[4 * v], sreg[4 * v + 1],
                                sreg[4 * v + 2], sreg[4 * v + 3]);
    }
}

// ---------------------------------------------------------------------------
extern "C" void kernel_launch(void* const* d_in, const int* in_sizes, int n_in,
                              void* d_out, int out_size)
{
    const float* X    = (const float*)d_in[0];
    const float* mask = (const float*)d_in[1];
    const float* Ws   = (const float*)d_in[2];
    const float* bs   = (const float*)d_in[3];
    const float* We   = (const float*)d_in[4];
    const float* be   = (const float*)d_in[5];
    float* out        = (float*)d_out;

    split_x<<<(1024 * 1024 + 255) / 256, 256>>>(X);
    split_wT<<<dim3(PADN / 32, HIN / 32, 2), dim3(32, 32)>>>(Ws, We);
    trig_table<<<(LL * (DD / 2) + 255) / 256, 256>>>();

    gemm_wmma<<<dim3(PADN / 64, 1024 / 128, 2), 256>>>(bs, be);

    conj_kernel<<<(BB * NMASK + 7) / 8, 256>>>();

    fused_kernel<<<dim3(LL / 16, LL / 16), 256>>>(mask, out);
}

// round 11
// speedup vs baseline: 1.4893x; 1.2508x over previous
#include <cuda_runtime.h>
#include <cuda_bf16.h>
#include <mma.h>
#include <cstdint>
#include <cstddef>

using namespace nvcuda;

#define BB   2
#define LL   512
#define HIN  1024
#define ENT  16
#define DD   50
#define TOT  850
#define PADN 896
#define NMASK 511
#define SCALE 0.14142135623730951f

// ---------------------------------------------------------------------------
// Scratch (device globals)
// ---------------------------------------------------------------------------
__device__ __nv_bfloat16 g_Xh[1024 * 1024];
__device__ __nv_bfloat16 g_Xl[1024 * 1024];
__device__ __nv_bfloat16 g_WhT[2 * PADN * HIN];   // [z][n][k]
__device__ __nv_bfloat16 g_WlT[2 * PADN * HIN];
__device__ float g_proj_s[BB * (ENT + 1) * LL * DD];
__device__ float g_proj_e[BB * (ENT + 1) * LL * DD];
__device__ float g_cd[BB * NMASK];
__device__ float g_fm[BB][LL * LL];               // final_mask (2MB)
__device__ float g_tcos[LL * (DD / 2)];
__device__ float g_tsin[LL * (DD / 2)];
// roped q/k, bf16 hi/lo, [b][e][i][64] (d padded 50->64 with zeros)
__device__ __nv_bfloat16 g_qh[BB * ENT * LL * 64];
__device__ __nv_bfloat16 g_ql[BB * ENT * LL * 64];
__device__ __nv_bfloat16 g_kh[BB * ENT * LL * 64];
__device__ __nv_bfloat16 g_kl[BB * ENT * LL * 64];

// ---------------------------------------------------------------------------
// Prep kernels
// ---------------------------------------------------------------------------
__global__ void split_x(const float* __restrict__ X)
{
    int idx = blockIdx.x * blockDim.x + threadIdx.x;
    if (idx >= 1024 * 1024) return;
    float x = X[idx];
    __nv_bfloat16 h = __float2bfloat16(x);
    __nv_bfloat16 l = __float2bfloat16(x - __bfloat162float(h));
    g_Xh[idx] = h;
    g_Xl[idx] = l;
}

__global__ void split_wT(const float* __restrict__ W0, const float* __restrict__ W1)
{
    __shared__ __nv_bfloat16 th[32][33];
    __shared__ __nv_bfloat16 tl[32][33];
    const int z = blockIdx.z;
    const float* W = z ? W1 : W0;
    const int n0 = blockIdx.x * 32;
    const int k0 = blockIdx.y * 32;
    const int tx = threadIdx.x, ty = threadIdx.y;

    int n = n0 + tx, k = k0 + ty;
    float x = (n < TOT) ? W[(size_t)k * TOT + n] : 0.f;
    __nv_bfloat16 h = __float2bfloat16(x);
    __nv_bfloat16 l = __float2bfloat16(x - __bfloat162float(h));
    th[ty][tx] = h;
    tl[ty][tx] = l;
    __syncthreads();

    int on = n0 + ty, ok = k0 + tx;
    size_t oidx = (size_t)z * PADN * HIN + (size_t)on * HIN + ok;
    g_WhT[oidx] = th[tx][ty];
    g_WlT[oidx] = tl[tx][ty];
}

__global__ void trig_table()
{
    int idx = blockIdx.x * blockDim.x + threadIdx.x;
    if (idx >= LL * (DD / 2)) return;
    int l = idx / (DD / 2), t = idx - l * (DD / 2);
    double inv = exp(-((2.0 * t) / (double)DD) * log(10000.0));
    double ang = (double)l * inv;
    g_tcos[idx] = (float)cos(ang);
    g_tsin[idx] = (float)sin(ang);
}

// ---------------------------------------------------------------------------
// WMMA bf16 GEMM (R8 128x64 config) + RoPE fused in epilogue.
// ---------------------------------------------------------------------------
union GemmSmem {
    struct {
        __nv_bfloat16 Ah[128][40];
        __nv_bfloat16 Al[128][40];
        __nv_bfloat16 Bh[64][40];
        __nv_bfloat16 Bl[64][40];
    } t;
    float out[128][68];
};

__global__ __launch_bounds__(256) void gemm_wmma(
    const float* __restrict__ bias0, const float* __restrict__ bias1)
{
    __shared__ GemmSmem sm;

    const int z  = blockIdx.z;
    const int n0 = blockIdx.x * 64;
    const int m0 = blockIdx.y * 128;
    const float* bias = z ? bias1 : bias0;
    float* dst        = z ? g_proj_e : g_proj_s;

    const int tid = threadIdx.x;
    const int wid = tid >> 5;
    const int wr = wid >> 1;
    const int wc = wid & 1;

    const uint4* Xh4 = reinterpret_cast<const uint4*>(g_Xh);
    const uint4* Xl4 = reinterpret_cast<const uint4*>(g_Xl);
    const uint4* Bh4 = reinterpret_cast<const uint4*>(g_WhT) + (size_t)z * PADN * 128;
    const uint4* Bl4 = reinterpret_cast<const uint4*>(g_WlT) + (size_t)z * PADN * 128;

    wmma::fragment<wmma::accumulator, 16, 16, 16, float> c[2][2];
    #pragma unroll
    for (int i = 0; i < 2; i++)
        #pragma unroll
        for (int j = 0; j < 2; j++)
            wmma::fill_fragment(c[i][j], 0.f);

    for (int kc = 0; kc < HIN; kc += 32) {
        const int kc8 = kc >> 3;
        #pragma unroll
        for (int it = 0; it < 2; it++) {
            int u = it * 256 + tid;
            int row = u >> 2, c8 = u & 3;
            size_t gi = (size_t)(m0 + row) * 128 + kc8 + c8;
            *reinterpret_cast<uint4*>(&sm.t.Ah[row][c8 * 8]) = Xh4[gi];
            *reinterpret_cast<uint4*>(&sm.t.Al[row][c8 * 8]) = Xl4[gi];
        }
        {
            int row = tid >> 2, c8 = tid & 3;
            size_t gi = (size_t)(n0 + row) * 128 + kc8 + c8;
            *reinterpret_cast<uint4*>(&sm.t.Bh[row][c8 * 8]) = Bh4[gi];
            *reinterpret_cast<uint4*>(&sm.t.Bl[row][c8 * 8]) = Bl4[gi];
        }
        __syncthreads();

        #pragma unroll
        for (int ks = 0; ks < 32; ks += 16) {
            wmma::fragment<wmma::matrix_a, 16, 16, 16, __nv_bfloat16, wmma::row_major> ah[2], al[2];
            wmma::fragment<wmma::matrix_b, 16, 16, 16, __nv_bfloat16, wmma::col_major> bh[2], bl[2];
            #pragma unroll
            for (int i = 0; i < 2; i++) {
                wmma::load_matrix_sync(ah[i], &sm.t.Ah[wr * 32 + i * 16][ks], 40);
                wmma::load_matrix_sync(al[i], &sm.t.Al[wr * 32 + i * 16][ks], 40);
            }
            #pragma unroll
            for (int j = 0; j < 2; j++) {
                wmma::load_matrix_sync(bh[j], &sm.t.Bh[wc * 32 + j * 16][ks], 40);
                wmma::load_matrix_sync(bl[j], &sm.t.Bl[wc * 32 + j * 16][ks], 40);
            }
            #pragma unroll
            for (int i = 0; i < 2; i++)
                #pragma unroll
                for (int j = 0; j < 2; j++) {
                    wmma::mma_sync(c[i][j], ah[i], bh[j], c[i][j]);
                    wmma::mma_sync(c[i][j], ah[i], bl[j], c[i][j]);
                    wmma::mma_sync(c[i][j], al[i], bh[j], c[i][j]);
                }
        }
        __syncthreads();
    }

    #pragma unroll
    for (int i = 0; i < 2; i++)
        #pragma unroll
        for (int j = 0; j < 2; j++)
            wmma::store_matrix_sync(&sm.out[wr * 32 + i * 16][wc * 32 + j * 16],
                                    c[i][j], 68, wmma::mem_row_major);
    __syncthreads();

    // Epilogue with fused RoPE (even/odd pair per thread; DD even)
    for (int idx = tid; idx < 128 * 32; idx += 256) {
        int row = idx >> 5, cp = idx & 31;
        int n = n0 + cp * 2;
        if (n < TOT) {
            int e = n / DD, d = n - e * DD;
            int m = m0 + row;
            int b = m >> 9, l = m & 511;
            float v0 = sm.out[row][cp * 2]     + bias[n];
            float v1 = sm.out[row][cp * 2 + 1] + bias[n + 1];
            if (e < ENT) {
                int t = d >> 1;
                float cc = g_tcos[l * (DD / 2) + t];
                float ss = g_tsin[l * (DD / 2) + t];
                float r0 = v0 * cc - v1 * ss;
                float r1 = v1 * cc + v0 * ss;
                v0 = r0; v1 = r1;
            }
            size_t o = (((size_t)b * (ENT + 1) + e) * LL + l) * DD + d;
            dst[o]     = v0;
            dst[o + 1] = v1;
        }
    }
}

// ---------------------------------------------------------------------------
// conj_diag — warp per (b,i), shfl reduce (e=16 slice is never roped)
// ---------------------------------------------------------------------------
__global__ __launch_bounds__(256) void conj_kernel()
{
    int wg = blockIdx.x * 8 + (threadIdx.x >> 5);
    int lane = threadIdx.x & 31;
    if (wg >= BB * NMASK) return;
    int b = wg / NMASK, i = wg - b * NMASK;
    const float* a = g_proj_s + (((size_t)b * (ENT + 1) + ENT) * LL + i) * DD;
    const float* c = g_proj_e + (((size_t)b * (ENT + 1) + ENT) * LL + (i + 1)) * DD;
    float s = 0.f;
    if (lane < DD)      s  = a[lane] * c[lane];
    if (lane + 32 < DD) s += a[lane + 32] * c[lane + 32];
    #pragma unroll
    for (int o = 16; o > 0; o >>= 1)
        s += __shfl_xor_sync(0xFFFFFFFFu, s, o);
    if (lane == 0) g_cd[wg] = s * SCALE;
}

// ---------------------------------------------------------------------------
// split_qk: roped fp32 q/k (e<16) -> bf16 hi/lo, [b][e][i][64], zero-pad d
// ---------------------------------------------------------------------------
__global__ void split_qk()
{
    int idx = blockIdx.x * blockDim.x + threadIdx.x;
    const int total = BB * ENT * LL * 64;
    if (idx >= total) return;
    int d = idx & 63;
    int r = idx >> 6;
    int i = r & 511;  r >>= 9;
    int e = r & 15;   int b = r >> 4;

    float q = 0.f, k = 0.f;
    if (d < DD) {
        size_t src = (((size_t)b * (ENT + 1) + e) * LL + i) * DD + d;
        q = g_proj_s[src];
        k = g_proj_e[src];
    }
    __nv_bfloat16 qh = __float2bfloat16(q);
    __nv_bfloat16 kh = __float2bfloat16(k);
    g_qh[idx] = qh;
    g_ql[idx] = __float2bfloat16(q - __bfloat162float(qh));
    g_kh[idx] = kh;
    g_kl[idx] = __float2bfloat16(k - __bfloat162float(kh));
}

// ---------------------------------------------------------------------------
// mask_kernel — R1 mask phase exactly (measured-fast shape), writes g_fm.
// 16x16 tile, 1024 blocks, 256 threads, scalar loads unrolled x8.
// ---------------------------------------------------------------------------
__global__ __launch_bounds__(256) void mask_kernel(const float* __restrict__ mask)
{
    __shared__ float scd[BB * NMASK];
    const int tid = threadIdx.x;
    const int tx = tid & 15, ty = tid >> 4;

    for (int k = tid; k < BB * NMASK; k += 256) scd[k] = g_cd[k];

    const int i0 = blockIdx.y * 16, j0 = blockIdx.x * 16;
    const int i = i0 + ty, j = j0 + tx;
    const float* mp = mask + (size_t)i * LL + j;

    __syncthreads();

    float a0 = 0.f, a1 = 0.f;
    int k = 0;
    for (; k + 8 <= NMASK; k += 8) {
        float m[8];
        #pragma unroll
        for (int u = 0; u < 8; u++) m[u] = mp[(size_t)(k + u) * (LL * LL)];
        #pragma unroll
        for (int u = 0; u < 8; u++) {
            a0 = fmaf(scd[k + u],          m[u], a0);
            a1 = fmaf(scd[NMASK + k + u],  m[u], a1);
        }
    }
    for (; k < NMASK; k++) {
        float m = mp[(size_t)k * (LL * LL)];
        a0 = fmaf(scd[k],         m, a0);
        a1 = fmaf(scd[NMASK + k], m, a1);
    }

    g_fm[0][(size_t)i * LL + j] = a0;
    g_fm[1][(size_t)i * LL + j] = a1;
}

// ---------------------------------------------------------------------------
// scores_wmma: per block (b, 32i x 32j), all 16 e via split-bf16 WMMA.
// 8 passes x 2e; 8 warps, each one 16x16 quadrant of one e, K=64.
// sS[16][32][36] fp32, then coalesced float4 x4 epilogue with +fm.
// Dynamic smem: sS (73728B) + tiles (2qk x 2e x 2hl x 32 x 72 bf16 = 36864B).
// ---------------------------------------------------------------------------
#define SS_LD   36
#define TILE_LD 72
#define SMEM_SS_BYTES   (16 * 32 * SS_LD * 4)          // 73728
#define SMEM_TILE_BYTES (8 * 32 * TILE_LD * 2)         // 36864
#define SCORES_SMEM     (SMEM_SS_BYTES + SMEM_TILE_BYTES)

__global__ __launch_bounds__(256) void scores_wmma(float* __restrict__ out)
{
    extern __shared__ char smem[];
    float* sS = reinterpret_cast<float*>(smem);
    __nv_bfloat16* tiles = reinterpret_cast<__nv_bfloat16*>(smem + SMEM_SS_BYTES);

    const int tid = threadIdx.x;
    const int wid = tid >> 5;
    const int j0 = blockIdx.x * 32;
    const int i0 = blockIdx.y * 32;
    const int b  = blockIdx.z;

    const uint4* qh4 = reinterpret_cast<const uint4*>(g_qh);
    const uint4* ql4 = reinterpret_cast<const uint4*>(g_ql);
    const uint4* kh4 = reinterpret_cast<const uint4*>(g_kh);
    const uint4* kl4 = reinterpret_cast<const uint4*>(g_kl);

    for (int ep = 0; ep < 8; ep++) {
        const int e0 = ep * 2;
        __syncthreads();   // protect tiles from previous pass's readers
        // load 8 matrices (qk x e x hl), each 32 rows x 64 bf16 (8 uint4/row)
        #pragma unroll
        for (int it = 0; it < 8; it++) {
            int g = it * 256 + tid;
            int c   = g & 7;
            int r   = (g >> 3) & 31;
            int mat = g >> 8;             // 0..7
            int hl = mat & 1, el = (mat >> 1) & 1, qk = mat >> 2;
            const uint4* src = qk ? (hl ? kl4 : kh4) : (hl ? ql4 : qh4);
            int row0 = qk ? j0 : i0;
            size_t gi = ((size_t)(b * ENT + e0 + el) * LL + row0 + r) * 8 + c;
            uint4 v = src[gi];
            *reinterpret_cast<uint4*>(
                &tiles[((qk * 4 + el * 2 + hl) * 32 + r) * TILE_LD + c * 8]) = v;
        }
        __syncthreads();

        // 8 warps: el = wid>>2 (which e), quad = wid&3 (output quadrant)
        const int el  = wid >> 2;
        const int qi  = ((wid >> 1) & 1) * 16;
        const int qj  = (wid & 1) * 16;
        const __nv_bfloat16* Qh_ = &tiles[((el * 2 + 0) * 32 + qi) * TILE_LD];
        const __nv_bfloat16* Ql_ = &tiles[((el * 2 + 1) * 32 + qi) * TILE_LD];
        const __nv_bfloat16* Kh_ = &tiles[((4 + el * 2 + 0) * 32 + qj) * TILE_LD];
        const __nv_bfloat16* Kl_ = &tiles[((4 + el * 2 + 1) * 32 + qj) * TILE_LD];

        wmma::fragment<wmma::accumulator, 16, 16, 16, float> acc;
        wmma::fill_fragment(acc, 0.f);
        #pragma unroll
        for (int ks = 0; ks < 64; ks += 16) {
            wmma::fragment<wmma::matrix_a, 16, 16, 16, __nv_bfloat16, wmma::row_major> ah, al;
            wmma::fragment<wmma::matrix_b, 16, 16, 16, __nv_bfloat16, wmma::col_major> bh, bl;
            wmma::load_matrix_sync(ah, Qh_ + ks, TILE_LD);
            wmma::load_matrix_sync(al, Ql_ + ks, TILE_LD);
            wmma::load_matrix_sync(bh, Kh_ + ks, TILE_LD);
            wmma::load_matrix_sync(bl, Kl_ + ks, TILE_LD);
            wmma::mma_sync(acc, ah, bh, acc);
            wmma::mma_sync(acc, ah, bl, acc);
            wmma::mma_sync(acc, al, bh, acc);
        }
        wmma::store_matrix_sync(&sS[(e0 + el) * 32 * SS_LD + qi * SS_LD + qj],
                                acc, SS_LD, wmma::mem_row_major);
    }
    __syncthreads();

    // Epilogue: out[b, i, j, 0..15] = sS * SCALE + fm, float4 x4 per cell
    for (int v = 0; v < 4; v++) {
        int lin = v * 256 + tid;           // 1024 cells
        int jj = lin & 31, ii = lin >> 5;
        int i = i0 + ii, j = j0 + jj;
        float fm = g_fm[b][(size_t)i * LL + j];
        float* op = out + ((((size_t)b * LL + i) * LL + j) * ENT);
        const float* sp = &sS[ii * SS_LD + jj];
        #pragma unroll
        for (int q = 0; q < 4; q++) {
            float4 w;
            w.x = fmaf(sp[(4 * q + 0) * 32 * SS_LD], SCALE, fm);
            w.y = fmaf(sp[(4 * q + 1) * 32 * SS_LD], SCALE, fm);
            w.z = fmaf(sp[(4 * q + 2) * 32 * SS_LD], SCALE, fm);
            w.w = fmaf(sp[(4 * q + 3) * 32 * SS_LD], SCALE, fm);
            *reinterpret_cast<float4*>(op + 4 * q) = w;
        }
    }
}

// ---------------------------------------------------------------------------
extern "C" void kernel_launch(void* const* d_in, const int* in_sizes, int n_in,
                              void* d_out, int out_size)
{
    const float* X    = (const float*)d_in[0];
    const float* mask = (const float*)d_in[1];
    const float* Ws   = (const float*)d_in[2];
    const float* bs   = (const float*)d_in[3];
    const float* We   = (const float*)d_in[4];
    const float* be   = (const float*)d_in[5];
    float* out        = (float*)d_out;

    cudaFuncSetAttribute(scores_wmma,
        cudaFuncAttributeMaxDynamicSharedMemorySize, SCORES_SMEM);

    split_x<<<(1024 * 1024 + 255) / 256, 256>>>(X);
    split_wT<<<dim3(PADN / 32, HIN / 32, 2), dim3(32, 32)>>>(Ws, We);
    trig_table<<<(LL * (DD / 2) + 255) / 256, 256>>>();

    gemm_wmma<<<dim3(PADN / 64, 1024 / 128, 2), 256>>>(bs, be);

    conj_kernel<<<(BB * NMASK + 7) / 8, 256>>>();
    split_qk<<<(BB * ENT * LL * 64 + 255) / 256, 256>>>();

    mask_kernel<<<dim3(LL / 16, LL / 16), 256>>>(mask);
    scores_wmma<<<dim3(LL / 32, LL / 32, 2), 256, SCORES_SMEM>>>(out);
}